// round 1
// baseline (speedup 1.0000x reference)
#include <cuda_runtime.h>

// CoCov: sum over 9 tile-shifts of per-16x16-tile zero-padded 3x3 convs, 64->64 ch.
// out[b,co,t1*16+i,t2*16+j] =
//   sum_{k=(r,c)} sum_ci sum_{dh,dw} K[k,co,ci,dh,dw] * tile(b,ci,t1+r-1,t2+c-1)[i+dh-1,j+dw-1]
// with tile-internal zero padding and zero tiles outside the 16x16 tile grid.

#define NTOT (9*64*64*9)

// weights transposed to [ci][k][tap][co] for coalesced per-ci staging
__device__ float g_wt[64 * 9 * 9 * 64];

__global__ void transpose_weights_kernel(const float* __restrict__ K) {
    int idx = blockIdx.x * blockDim.x + threadIdx.x;
    if (idx >= NTOT) return;
    // source layout: [k][co][ci][dh][dw], idx = ((k*64+co)*64+ci)*9 + tap
    int tap = idx % 9;
    int t = idx / 9;
    int ci = t & 63; t >>= 6;
    int co = t & 63; t >>= 6;
    int k = t;
    g_wt[((ci * 9 + k) * 9 + tap) * 64 + co] = K[idx];
}

__global__ __launch_bounds__(256, 2)
void cocov_kernel(const float* __restrict__ inp, float* __restrict__ out) {
    // 9 input tiles, each 16x16 stored inside an 18x18 zero-bordered frame
    __shared__ __align__(16) float s_in[9][18][18];
    // weights for current ci: [k][tap][co]
    __shared__ __align__(16) float s_w[9 * 9 * 64];

    const int t2 = blockIdx.x;      // tile col
    const int t1 = blockIdx.y;      // tile row
    const int b  = blockIdx.z;      // batch
    const int tid  = threadIdx.x;
    const int lane = tid & 31;
    const int wid  = tid >> 5;
    const int cobase = wid << 3;          // each warp: 8 output channels
    const int i0 = (lane >> 4);           // 0/1 : pixel row parity within pair
    const int j  = lane & 15;             // pixel col

    // zero the padded input frames once; interiors are rewritten every ci,
    // borders stay zero for the whole kernel.
    {
        float* f = &s_in[0][0][0];
        for (int e = tid; e < 9 * 18 * 18; e += 256) f[e] = 0.f;
    }

    // loader mapping: thread -> (row ii, col jj) of a 16x16 tile
    const int ii = tid >> 4;
    const int jj = tid & 15;

    // per-tile global base offsets + validity mask (tiles outside grid are zero)
    int base[9];
    unsigned vmask = 0;
    #pragma unroll
    for (int kt = 0; kt < 9; kt++) {
        int r = kt / 3, c = kt % 3;
        int tt1 = t1 + r - 1, tt2 = t2 + c - 1;
        if (tt1 >= 0 && tt1 < 16 && tt2 >= 0 && tt2 < 16) vmask |= (1u << kt);
        base[kt] = ((b * 64) * 256 + tt1 * 16 + ii) * 256 + tt2 * 16 + jj;
    }

    // 8 pixels (rows 2q+i0, col j) x 8 channels per thread
    float acc[8][8];
    #pragma unroll
    for (int q = 0; q < 8; q++)
        #pragma unroll
        for (int o = 0; o < 8; o++) acc[q][o] = 0.f;

    for (int ci = 0; ci < 64; ci++) {
        __syncthreads();

        // stage 9 input tiles for this ci
        const int cioff = ci * 256 * 256;
        #pragma unroll
        for (int kt = 0; kt < 9; kt++) {
            float v = ((vmask >> kt) & 1) ? __ldg(inp + base[kt] + cioff) : 0.f;
            s_in[kt][ii + 1][jj + 1] = v;
        }

        // stage weights for this ci (coalesced float4)
        {
            const float4* ws4 = (const float4*)(g_wt + ci * (9 * 9 * 64));
            float4* sw4 = (float4*)s_w;
            for (int e = tid; e < (9 * 9 * 64) / 4; e += 256) sw4[e] = ws4[e];
        }
        __syncthreads();

        #pragma unroll 1
        for (int kt = 0; kt < 9; kt++) {
            const float* tin = &s_in[kt][0][0];
            const float* tw  = &s_w[kt * 576 + cobase];
            #pragma unroll
            for (int tap = 0; tap < 9; tap++) {
                const int dh = tap / 3, dw = tap % 3;
                // warp-broadcast weight loads (all lanes same address)
                float4 w0 = *(const float4*)(tw + tap * 64);
                float4 w1 = *(const float4*)(tw + tap * 64 + 4);
                float x[8];
                #pragma unroll
                for (int q = 0; q < 8; q++)
                    x[q] = tin[(2 * q + i0 + dh) * 18 + (j + dw)];
                #pragma unroll
                for (int q = 0; q < 8; q++) {
                    acc[q][0] = fmaf(x[q], w0.x, acc[q][0]);
                    acc[q][1] = fmaf(x[q], w0.y, acc[q][1]);
                    acc[q][2] = fmaf(x[q], w0.z, acc[q][2]);
                    acc[q][3] = fmaf(x[q], w0.w, acc[q][3]);
                    acc[q][4] = fmaf(x[q], w1.x, acc[q][4]);
                    acc[q][5] = fmaf(x[q], w1.y, acc[q][5]);
                    acc[q][6] = fmaf(x[q], w1.z, acc[q][6]);
                    acc[q][7] = fmaf(x[q], w1.w, acc[q][7]);
                }
            }
        }
    }

    // epilogue: out[b, cobase+o, t1*16 + 2q+i0, t2*16 + j]
    const size_t obase =
        ((size_t)(b * 64 + cobase) * 256 + (size_t)(t1 * 16 + i0)) * 256 + t2 * 16 + j;
    #pragma unroll
    for (int o = 0; o < 8; o++) {
        #pragma unroll
        for (int q = 0; q < 8; q++) {
            out[obase + (size_t)o * 65536 + (size_t)q * 512] = acc[q][o];
        }
    }
}

extern "C" void kernel_launch(void* const* d_in, const int* in_sizes, int n_in,
                              void* d_out, int out_size) {
    const float* inp = (const float*)d_in[0];   // (8, 64, 256, 256) fp32
    const float* ker = (const float*)d_in[1];   // (9, 64, 64, 3, 3) fp32
    float* out = (float*)d_out;                 // (8, 64, 256, 256) fp32

    transpose_weights_kernel<<<(NTOT + 255) / 256, 256>>>(ker);

    dim3 grid(16, 16, 8);   // (t2, t1, b)
    cocov_kernel<<<grid, 256>>>(inp, out);
}